// round 4
// baseline (speedup 1.0000x reference)
#include <cuda_runtime.h>
#include <mma.h>
#include <cstdio>

using namespace nvcuda;

#define N_FACES 40000
#define N_EDGES 60000
#define NNZ     120000
#define CH      512
#define M_PAD   40064   // 313 * 128, padded row count for GEMM tiles

// ---------------- scratch (static device globals; no allocation) -------------
__device__ float g_S1[(size_t)M_PAD * CH];   // x @ W1              (padded)
__device__ float g_H [(size_t)N_EDGES * CH]; // sigmoid(spmm/deg_e)
__device__ float g_T [(size_t)M_PAD * CH];   // B2^T @ h            (padded)
__device__ float g_Y [(size_t)M_PAD * CH];   // T @ W2              (padded)
__device__ float g_deg_e[N_EDGES];
__device__ float g_deg_f[N_FACES];

__device__ __forceinline__ float sigf(float x) {
    return 1.0f / (1.0f + __expf(-x));
}

// ---------------- degree kernels ---------------------------------------------
__global__ void zero_degs_kernel() {
    int i = blockIdx.x * blockDim.x + threadIdx.x;
    if (i < N_EDGES) g_deg_e[i] = 0.0f;
    if (i < N_FACES) g_deg_f[i] = 0.0f;
}

__global__ void degs_kernel(const int* __restrict__ ei, const int* __restrict__ fi,
                            const float* __restrict__ vals) {
    int i = blockIdx.x * blockDim.x + threadIdx.x;
    if (i < NNZ) {
        float v = vals[i];
        atomicAdd(&g_deg_e[ei[i]], v);
        atomicAdd(&g_deg_f[fi[i]], v);
    }
}

// ---------------- TF32 tensor-core GEMM: C[MxN] = A[MxK] @ B[KxN] -------------
// K = N = 512 fixed. Block tile 128x128, BK=32. 256 threads = 8 warps (4x2),
// warp tile 32x64 (2x4 fragments of 16x16x8 tf32).
constexpr int BM = 128, BN = 128, BK = 32;

__global__ __launch_bounds__(256)
void gemm_tf32(const float* __restrict__ A, const float* __restrict__ B,
               float* __restrict__ C, int M_real) {
    const int K = CH, N = CH;
    __shared__ float As[BM][BK + 4];   // ld = 36 (mult of 4, 16B-aligned rows)
    __shared__ float Bs[BK][BN + 4];   // ld = 132

    const int tid  = threadIdx.x;
    const int warp = tid >> 5;
    const int wm   = warp >> 1;   // 0..3 -> M
    const int wn   = warp & 1;    // 0..1 -> N
    const int blockM = blockIdx.y * BM;
    const int blockN = blockIdx.x * BN;

    wmma::fragment<wmma::accumulator, 16, 16, 8, float> acc[2][4];
#pragma unroll
    for (int i = 0; i < 2; i++)
#pragma unroll
        for (int j = 0; j < 4; j++) wmma::fill_fragment(acc[i][j], 0.0f);

    for (int k0 = 0; k0 < K; k0 += BK) {
        // A tile: 128x32 floats = 1024 float4, 4 per thread
#pragma unroll
        for (int l = 0; l < 4; l++) {
            int idx = tid + l * 256;
            int r = idx >> 3;
            int c = (idx & 7) * 4;
            int grow = blockM + r;
            float4 v = make_float4(0.f, 0.f, 0.f, 0.f);
            if (grow < M_real)
                v = *reinterpret_cast<const float4*>(A + (size_t)grow * K + k0 + c);
            *reinterpret_cast<float4*>(&As[r][c]) = v;
        }
        // B tile: 32x128 floats = 1024 float4
#pragma unroll
        for (int l = 0; l < 4; l++) {
            int idx = tid + l * 256;
            int r = idx >> 5;
            int c = (idx & 31) * 4;
            float4 v = *reinterpret_cast<const float4*>(B + (size_t)(k0 + r) * N + blockN + c);
            *reinterpret_cast<float4*>(&Bs[r][c]) = v;
        }
        __syncthreads();

#pragma unroll
        for (int kk = 0; kk < BK; kk += 8) {
            wmma::fragment<wmma::matrix_a, 16, 16, 8, wmma::precision::tf32, wmma::row_major> af[2];
            wmma::fragment<wmma::matrix_b, 16, 16, 8, wmma::precision::tf32, wmma::row_major> bf[4];
#pragma unroll
            for (int i = 0; i < 2; i++) {
                wmma::load_matrix_sync(af[i], &As[wm * 32 + i * 16][kk], BK + 4);
#pragma unroll
                for (int t = 0; t < af[i].num_elements; t++)
                    af[i].x[t] = wmma::__float_to_tf32(af[i].x[t]);
            }
#pragma unroll
            for (int j = 0; j < 4; j++) {
                wmma::load_matrix_sync(bf[j], &Bs[kk][wn * 64 + j * 16], BN + 4);
#pragma unroll
                for (int t = 0; t < bf[j].num_elements; t++)
                    bf[j].x[t] = wmma::__float_to_tf32(bf[j].x[t]);
            }
#pragma unroll
            for (int i = 0; i < 2; i++)
#pragma unroll
                for (int j = 0; j < 4; j++)
                    wmma::mma_sync(acc[i][j], af[i], bf[j], acc[i][j]);
        }
        __syncthreads();
    }

    // C is padded scratch -> unguarded stores
#pragma unroll
    for (int i = 0; i < 2; i++)
#pragma unroll
        for (int j = 0; j < 4; j++)
            wmma::store_matrix_sync(
                C + (size_t)(blockM + wm * 32 + i * 16) * N + blockN + wn * 64 + j * 16,
                acc[i][j], N, wmma::mem_row_major);
}

// ---------------- per-edge: h = sigmoid(spmm(S1) / deg_e) --------------------
// edge_idx[i] = i % N_EDGES  =>  nnz for edge e at i = e and i = e + N_EDGES
__global__ void edge_kernel(const int* __restrict__ fi, const float* __restrict__ vals) {
    int t = blockIdx.x * blockDim.x + threadIdx.x;   // N_EDGES * 128 threads
    int e = t >> 7;
    int c = (t & 127) * 4;
    if (e >= N_EDGES) return;
    int f1 = fi[e];
    int f2 = fi[e + N_EDGES];
    float v1 = vals[e];
    float v2 = vals[e + N_EDGES];
    float inv = 1.0f / g_deg_e[e];
    float4 a = *reinterpret_cast<const float4*>(g_S1 + (size_t)f1 * CH + c);
    float4 b = *reinterpret_cast<const float4*>(g_S1 + (size_t)f2 * CH + c);
    float4 o;
    o.x = sigf((v1 * a.x + v2 * b.x) * inv);
    o.y = sigf((v1 * a.y + v2 * b.y) * inv);
    o.z = sigf((v1 * a.z + v2 * b.z) * inv);
    o.w = sigf((v1 * a.w + v2 * b.w) * inv);
    *reinterpret_cast<float4*>(g_H + (size_t)e * CH + c) = o;
}

// ---------------- per-face: T[f] = sum_j vals[3f+j] * h[edge_idx[3f+j]] -------
__global__ void face_kernel(const int* __restrict__ ei, const float* __restrict__ vals) {
    int t = blockIdx.x * blockDim.x + threadIdx.x;   // M_PAD * 128 threads
    int f = t >> 7;
    int c = (t & 127) * 4;
    if (f >= M_PAD) return;
    float4 o = make_float4(0.f, 0.f, 0.f, 0.f);
    if (f < N_FACES) {
#pragma unroll
        for (int j = 0; j < 3; j++) {
            int e  = ei[3 * f + j];
            float v = vals[3 * f + j];
            float4 h = *reinterpret_cast<const float4*>(g_H + (size_t)e * CH + c);
            o.x += v * h.x; o.y += v * h.y; o.z += v * h.z; o.w += v * h.w;
        }
    }
    *reinterpret_cast<float4*>(g_T + (size_t)f * CH + c) = o;
}

// ---------------- output: out = sigmoid(Y / deg_f) ----------------------------
__global__ void out_kernel(float* __restrict__ out) {
    int t = blockIdx.x * blockDim.x + threadIdx.x;   // N_FACES * 128 threads
    int f = t >> 7;
    int c = (t & 127) * 4;
    if (f >= N_FACES) return;
    float inv = 1.0f / g_deg_f[f];
    float4 y = *reinterpret_cast<const float4*>(g_Y + (size_t)f * CH + c);
    float4 o;
    o.x = sigf(y.x * inv);
    o.y = sigf(y.y * inv);
    o.z = sigf(y.z * inv);
    o.w = sigf(y.w * inv);
    *reinterpret_cast<float4*>(out + (size_t)f * CH + c) = o;
}

// ------------------------------------------------------------------------------
extern "C" void kernel_launch(void* const* d_in, const int* in_sizes, int n_in,
                              void* d_out, int out_size) {
    (void)in_sizes; (void)n_in; (void)out_size;
    const float* x    = (const float*)d_in[0];
    const float* W1   = (const float*)d_in[1];
    const float* W2   = (const float*)d_in[2];
    const int*   ei   = (const int*)  d_in[3];
    const int*   fi   = (const int*)  d_in[4];
    const float* vals = (const float*)d_in[5];
    float* out = (float*)d_out;

    float *S1p, *Tp, *Yp;
    cudaGetSymbolAddress((void**)&S1p, g_S1);
    cudaGetSymbolAddress((void**)&Tp,  g_T);
    cudaGetSymbolAddress((void**)&Yp,  g_Y);

    // 1. degrees (re-zeroed every launch so graph replays are deterministic)
    zero_degs_kernel<<<(N_EDGES + 255) / 256, 256>>>();
    degs_kernel<<<(NNZ + 255) / 256, 256>>>(ei, fi, vals);

    // 2. S1 = x @ W1
    gemm_tf32<<<dim3(CH / BN, M_PAD / BM), 256>>>(x, W1, S1p, N_FACES);

    // 3. h = sigmoid(B2 @ S1 / deg_e)
    edge_kernel<<<(N_EDGES * 128) / 256, 256>>>(fi, vals);

    // 4. T = B2^T @ h   (aggregation hoisted before W2 by linearity)
    face_kernel<<<(M_PAD * 128) / 256, 256>>>(ei, vals);

    // 5. Y = T @ W2
    gemm_tf32<<<dim3(CH / BN, M_PAD / BM), 256>>>(Tp, W2, Yp, M_PAD);

    // 6. out = sigmoid(Y / deg_f)
    out_kernel<<<(N_FACES * 128) / 256, 256>>>(out);
}